// round 1
// baseline (speedup 1.0000x reference)
#include <cuda_runtime.h>
#include <cuda_bf16.h>

// x: [32, 256, 32, 16, 16] fp32 -> out: [32, 256, 32, 31, 4] fp32
// Tiles = 32*256*32 = 262144 independent 16x16 (h x w) blocks.
// BIN_NUM = [16,8,4,2,1] (height bins), WIDTH_TOKEN_NUM = 4.
// Bin row offsets in output dim-3: b=16 -> [0,16), b=8 -> [16,24),
// b=4 -> [24,28), b=2 -> [28,30), b=1 -> [30,31).

#define N_TILES (32 * 256 * 32)

__device__ __forceinline__ float4 f4add(float4 a, float4 b) {
    return make_float4(a.x + b.x, a.y + b.y, a.z + b.z, a.w + b.w);
}
__device__ __forceinline__ float4 f4max(float4 a, float4 b) {
    return make_float4(fmaxf(a.x, b.x), fmaxf(a.y, b.y),
                       fmaxf(a.z, b.z), fmaxf(a.w, b.w));
}
// token value from per-column z: mean over 4 cols + max over 4 cols,
// with z_c = sum_c * inv + max_c
__device__ __forceinline__ float token(float4 s, float4 m, float inv) {
    float zx = fmaf(s.x, inv, m.x);
    float zy = fmaf(s.y, inv, m.y);
    float zz = fmaf(s.z, inv, m.z);
    float zw = fmaf(s.w, inv, m.w);
    float mean = ((zx + zy) + (zz + zw)) * 0.25f;
    float mx = fmaxf(fmaxf(zx, zy), fmaxf(zz, zw));
    return mean + mx;
}

__global__ void __launch_bounds__(256)
hwtp_kernel(const float* __restrict__ x, float* __restrict__ out) {
    int gid  = blockIdx.x * 256 + threadIdx.x;   // 4 threads per tile
    int tile = gid >> 2;
    int t    = gid & 3;                          // width token id (4 cols each)

    // Row r, cols [4t, 4t+4): one aligned float4. Row stride = 16 floats = 4 float4.
    const float4* __restrict__ src =
        reinterpret_cast<const float4*>(x + (size_t)tile * 256) + t;
    float* __restrict__ dst = out + (size_t)tile * 124 + t;

    float4 s2s, s2m, s4s, s4m, s8s, s8m, s16s, s16m;

#pragma unroll
    for (int r = 0; r < 16; ++r) {
        float4 v = src[r * 4];

        // ---- b=16: bin of 1 row, z = 2*v  (sum=v, max=v, inv=1) ----
        dst[(0 + r) * 4] = token(v, v, 1.0f);

        if ((r & 1) == 0) {
            s2s = v; s2m = v;
        } else {
            // ---- b=8: bins of 2 rows ----
            s2s = f4add(s2s, v);
            s2m = f4max(s2m, v);
            dst[(16 + (r >> 1)) * 4] = token(s2s, s2m, 0.5f);

            if ((r & 3) == 1) {
                s4s = s2s; s4m = s2m;
            } else {
                // ---- b=4: bins of 4 rows ----
                s4s = f4add(s4s, s2s);
                s4m = f4max(s4m, s2m);
                dst[(24 + (r >> 2)) * 4] = token(s4s, s4m, 0.25f);

                if ((r & 7) == 3) {
                    s8s = s4s; s8m = s4m;
                } else {
                    // ---- b=2: bins of 8 rows ----
                    s8s = f4add(s8s, s4s);
                    s8m = f4max(s8m, s4m);
                    dst[(28 + (r >> 3)) * 4] = token(s8s, s8m, 0.125f);

                    if (r == 7) {
                        s16s = s8s; s16m = s8m;
                    } else if (r == 15) {
                        // ---- b=1: one bin of 16 rows ----
                        s16s = f4add(s16s, s8s);
                        s16m = f4max(s16m, s8m);
                        dst[30 * 4] = token(s16s, s16m, 0.0625f);
                    }
                }
            }
        }
    }
}

extern "C" void kernel_launch(void* const* d_in, const int* in_sizes, int n_in,
                              void* d_out, int out_size) {
    const float* x = (const float*)d_in[0];
    float* out = (float*)d_out;
    // 262144 tiles * 4 threads = 1,048,576 threads = 4096 blocks of 256 (exact)
    hwtp_kernel<<<(N_TILES * 4) / 256, 256>>>(x, out);
}

// round 2
// speedup vs baseline: 1.1499x; 1.1499x over previous
#include <cuda_runtime.h>
#include <cuda_bf16.h>

// x: [32, 256, 32, 16, 16] fp32 -> out: [32, 256, 32, 31, 4] fp32
// Tiles = 32*256*32 = 262144 independent 16x16 (h x w) blocks.
// BIN_NUM = [16,8,4,2,1] (height bins), WIDTH_TOKEN_NUM = 4.
// Bin row offsets in output dim-3: b=16 -> [0,16), b=8 -> [16,24),
// b=4 -> [24,28), b=2 -> [28,30), b=1 -> [30,31).
//
// R2: front-batch all 16 row loads (MLP_p1 = 16) to cover DRAM latency;
// compute + 31 scalar stores afterward. 4 threads per tile (one per width
// token), each loading one aligned float4 per row.

#define N_TILES (32 * 256 * 32)

__device__ __forceinline__ float4 f4add(float4 a, float4 b) {
    return make_float4(a.x + b.x, a.y + b.y, a.z + b.z, a.w + b.w);
}
__device__ __forceinline__ float4 f4max(float4 a, float4 b) {
    return make_float4(fmaxf(a.x, b.x), fmaxf(a.y, b.y),
                       fmaxf(a.z, b.z), fmaxf(a.w, b.w));
}
// token value from per-column (sum, max): z_c = sum_c * inv + max_c,
// token = mean_c(z) + max_c(z)
__device__ __forceinline__ float token(float4 s, float4 m, float inv) {
    float zx = fmaf(s.x, inv, m.x);
    float zy = fmaf(s.y, inv, m.y);
    float zz = fmaf(s.z, inv, m.z);
    float zw = fmaf(s.w, inv, m.w);
    float mean = ((zx + zy) + (zz + zw)) * 0.25f;
    float mx = fmaxf(fmaxf(zx, zy), fmaxf(zz, zw));
    return mean + mx;
}

__global__ void __launch_bounds__(256, 3)
hwtp_kernel(const float* __restrict__ x, float* __restrict__ out) {
    int gid  = blockIdx.x * 256 + threadIdx.x;   // 4 threads per tile
    int tile = gid >> 2;
    int t    = gid & 3;                          // width token id (4 cols each)

    // Row r, cols [4t, 4t+4): one aligned float4. Row stride = 16 floats = 4 float4.
    const float4* __restrict__ src =
        reinterpret_cast<const float4*>(x + (size_t)tile * 256) + t;
    float* __restrict__ dst = out + (size_t)tile * 124 + t;

    // ---- Phase 1: issue ALL loads up front (MLP_p1 = 16) ----
    float4 v[16];
#pragma unroll
    for (int r = 0; r < 16; ++r) {
        v[r] = src[r * 4];
    }

    // ---- Phase 2: hierarchical (sum, max) pyramid + stores ----
    float4 s2s, s2m, s4s, s4m, s8s, s8m, s16s, s16m;

#pragma unroll
    for (int r = 0; r < 16; ++r) {
        float4 w = v[r];

        // b=16: bin of 1 row (sum=v, max=v, inv=1)
        dst[(0 + r) * 4] = token(w, w, 1.0f);

        if ((r & 1) == 0) {
            s2s = w; s2m = w;
        } else {
            // b=8: bins of 2 rows
            s2s = f4add(s2s, w);
            s2m = f4max(s2m, w);
            dst[(16 + (r >> 1)) * 4] = token(s2s, s2m, 0.5f);

            if ((r & 3) == 1) {
                s4s = s2s; s4m = s2m;
            } else {
                // b=4: bins of 4 rows
                s4s = f4add(s4s, s2s);
                s4m = f4max(s4m, s2m);
                dst[(24 + (r >> 2)) * 4] = token(s4s, s4m, 0.25f);

                if ((r & 7) == 3) {
                    s8s = s4s; s8m = s4m;
                } else {
                    // b=2: bins of 8 rows
                    s8s = f4add(s8s, s4s);
                    s8m = f4max(s8m, s4m);
                    dst[(28 + (r >> 3)) * 4] = token(s8s, s8m, 0.125f);

                    if (r == 7) {
                        s16s = s8s; s16m = s8m;
                    } else if (r == 15) {
                        // b=1: one bin of 16 rows
                        s16s = f4add(s16s, s8s);
                        s16m = f4max(s16m, s8m);
                        dst[30 * 4] = token(s16s, s16m, 0.0625f);
                    }
                }
            }
        }
    }
}

extern "C" void kernel_launch(void* const* d_in, const int* in_sizes, int n_in,
                              void* d_out, int out_size) {
    const float* x = (const float*)d_in[0];
    float* out = (float*)d_out;
    // 262144 tiles * 4 threads = 1,048,576 threads = 4096 blocks of 256 (exact)
    hwtp_kernel<<<(N_TILES * 4) / 256, 256>>>(x, out);
}

// round 4
// speedup vs baseline: 1.2773x; 1.1108x over previous
#include <cuda_runtime.h>
#include <cuda_bf16.h>

// x: [32, 256, 32, 16, 16] fp32 -> out: [32, 256, 32, 31, 4] fp32
// Tiles = 32*256*32 = 262144 independent 16x16 (h x w) blocks.
// BIN_NUM = [16,8,4,2,1] (height bins), WIDTH_TOKEN_NUM = 4.
// Output dim-3 offsets: b=16 -> [0,16), b=8 -> [16,24), b=4 -> [24,28),
// b=2 -> [28,30), b=1 -> [30,31).
//
// R3: 8 threads per tile — thread = (width token t in 0..3, row half in 0..1).
// Each thread front-batches 8 float4 loads (rows half*8 .. half*8+7), computes
// the pyramid through b=2 locally, and combines b=1 across half-partners via
// __shfl_xor_sync(lane^4). Halved register footprint -> 64-reg cap, 50% occ.

#define N_TILES (32 * 256 * 32)

__device__ __forceinline__ float4 f4add(float4 a, float4 b) {
    return make_float4(a.x + b.x, a.y + b.y, a.z + b.z, a.w + b.w);
}
__device__ __forceinline__ float4 f4max(float4 a, float4 b) {
    return make_float4(fmaxf(a.x, b.x), fmaxf(a.y, b.y),
                       fmaxf(a.z, b.z), fmaxf(a.w, b.w));
}
// token from per-column (sum, max): z_c = sum_c * inv + max_c,
// token = mean_c(z) + max_c(z)
__device__ __forceinline__ float token(float4 s, float4 m, float inv) {
    float zx = fmaf(s.x, inv, m.x);
    float zy = fmaf(s.y, inv, m.y);
    float zz = fmaf(s.z, inv, m.z);
    float zw = fmaf(s.w, inv, m.w);
    float mean = ((zx + zy) + (zz + zw)) * 0.25f;
    float mx = fmaxf(fmaxf(zx, zy), fmaxf(zz, zw));
    return mean + mx;
}

__global__ void __launch_bounds__(256, 4)
hwtp_kernel(const float* __restrict__ x, float* __restrict__ out) {
    int gid  = blockIdx.x * 256 + threadIdx.x;
    int t    = gid & 3;            // width token (4 cols)
    int half = (gid >> 2) & 1;     // row half: rows [half*8, half*8+8)
    int tile = gid >> 3;

    // float4 view of the tile: 64 float4; row stride = 4 float4.
    const float4* __restrict__ src =
        reinterpret_cast<const float4*>(x + (size_t)tile * 256) + half * 32 + t;
    float* __restrict__ dst = out + (size_t)tile * 124 + t;

    // ---- Phase 1: all 8 loads up front ----
    float4 v[8];
#pragma unroll
    for (int r = 0; r < 8; ++r) {
        v[r] = src[r * 4];
    }

    // ---- Phase 2: local pyramid (rows half*8 .. half*8+7) ----
    float4 s2s, s2m, s4s, s4m, s8s, s8m;

#pragma unroll
    for (int r = 0; r < 8; ++r) {
        float4 w = v[r];

        // b=16: single-row bins
        dst[(half * 8 + r) * 4] = token(w, w, 1.0f);

        if ((r & 1) == 0) {
            s2s = w; s2m = w;
        } else {
            // b=8: 2-row bins
            s2s = f4add(s2s, w);
            s2m = f4max(s2m, w);
            dst[(16 + half * 4 + (r >> 1)) * 4] = token(s2s, s2m, 0.5f);

            if ((r & 3) == 1) {
                s4s = s2s; s4m = s2m;
            } else {
                // b=4: 4-row bins
                s4s = f4add(s4s, s2s);
                s4m = f4max(s4m, s2m);
                dst[(24 + half * 2 + (r >> 2)) * 4] = token(s4s, s4m, 0.25f);

                if (r == 3) {
                    s8s = s4s; s8m = s4m;
                } else if (r == 7) {
                    // b=2: 8-row bins (this thread's whole half)
                    s8s = f4add(s8s, s4s);
                    s8m = f4max(s8m, s4m);
                    dst[(28 + half) * 4] = token(s8s, s8m, 0.125f);
                }
            }
        }
    }

    // ---- b=1: combine the two halves via shuffle (lane ^ 4 flips `half`) ----
    float4 os, om;
    os.x = __shfl_xor_sync(0xffffffffu, s8s.x, 4);
    os.y = __shfl_xor_sync(0xffffffffu, s8s.y, 4);
    os.z = __shfl_xor_sync(0xffffffffu, s8s.z, 4);
    os.w = __shfl_xor_sync(0xffffffffu, s8s.w, 4);
    om.x = __shfl_xor_sync(0xffffffffu, s8m.x, 4);
    om.y = __shfl_xor_sync(0xffffffffu, s8m.y, 4);
    om.z = __shfl_xor_sync(0xffffffffu, s8m.z, 4);
    om.w = __shfl_xor_sync(0xffffffffu, s8m.w, 4);

    if (half == 0) {
        float4 s16s = f4add(s8s, os);
        float4 s16m = f4max(s8m, om);
        dst[30 * 4] = token(s16s, s16m, 0.0625f);
    }
}

extern "C" void kernel_launch(void* const* d_in, const int* in_sizes, int n_in,
                              void* d_out, int out_size) {
    const float* x = (const float*)d_in[0];
    float* out = (float*)d_out;
    // 262144 tiles * 8 threads = 2,097,152 threads = 8192 blocks of 256 (exact)
    hwtp_kernel<<<(N_TILES * 8) / 256, 256>>>(x, out);
}

// round 6
// speedup vs baseline: 1.3017x; 1.0191x over previous
#include <cuda_runtime.h>
#include <cuda_bf16.h>

// x: [32, 256, 32, 16, 16] fp32 -> out: [32, 256, 32, 31, 4] fp32
// Tiles = 32*256*32 = 262144 independent 16x16 (h x w) blocks.
// BIN_NUM = [16,8,4,2,1] (height bins), WIDTH_TOKEN_NUM = 4.
// Output dim-3 offsets: b=16 -> [0,16), b=8 -> [16,24), b=4 -> [24,28),
// b=2 -> [28,30), b=1 -> [30,31).
//
// R4: 16 threads per tile — thread = (width token t in 0..3, quarter q in 0..3,
// rows [4q, 4q+4)). 4 front-batched float4 loads per thread, local pyramid
// through b=4, then shuffle combines: b=2 via lane^4 (quarter partner),
// b=1 via lane^8. Small reg footprint -> 6 blocks/SM (75% occ).

#define N_TILES (32 * 256 * 32)

__device__ __forceinline__ float4 f4add(float4 a, float4 b) {
    return make_float4(a.x + b.x, a.y + b.y, a.z + b.z, a.w + b.w);
}
__device__ __forceinline__ float4 f4max(float4 a, float4 b) {
    return make_float4(fmaxf(a.x, b.x), fmaxf(a.y, b.y),
                       fmaxf(a.z, b.z), fmaxf(a.w, b.w));
}
__device__ __forceinline__ float4 f4shfl_xor(float4 a, int m) {
    float4 r;
    r.x = __shfl_xor_sync(0xffffffffu, a.x, m);
    r.y = __shfl_xor_sync(0xffffffffu, a.y, m);
    r.z = __shfl_xor_sync(0xffffffffu, a.z, m);
    r.w = __shfl_xor_sync(0xffffffffu, a.w, m);
    return r;
}
// token from per-column (sum, max): z_c = sum_c * inv + max_c,
// token = mean_c(z) + max_c(z)
__device__ __forceinline__ float token(float4 s, float4 m, float inv) {
    float zx = fmaf(s.x, inv, m.x);
    float zy = fmaf(s.y, inv, m.y);
    float zz = fmaf(s.z, inv, m.z);
    float zw = fmaf(s.w, inv, m.w);
    float mean = ((zx + zy) + (zz + zw)) * 0.25f;
    float mx = fmaxf(fmaxf(zx, zy), fmaxf(zz, zw));
    return mean + mx;
}

__global__ void __launch_bounds__(256, 6)
hwtp_kernel(const float* __restrict__ x, float* __restrict__ out) {
    int gid  = blockIdx.x * 256 + threadIdx.x;
    int t    = gid & 3;            // width token (4 cols)
    int q    = (gid >> 2) & 3;     // row quarter: rows [4q, 4q+4)
    int tile = gid >> 4;

    // float4 view of the tile: 64 float4; row stride = 4 float4.
    const float4* __restrict__ src =
        reinterpret_cast<const float4*>(x + (size_t)tile * 256) + q * 16 + t;
    float* __restrict__ dst = out + (size_t)tile * 124 + t;

    // ---- Phase 1: all 4 loads up front ----
    float4 v[4];
#pragma unroll
    for (int r = 0; r < 4; ++r) {
        v[r] = src[r * 4];
    }

    // ---- Phase 2: local pyramid (rows 4q .. 4q+3) ----
    float4 s2s, s2m, s4s, s4m;

#pragma unroll
    for (int r = 0; r < 4; ++r) {
        float4 w = v[r];

        // b=16: single-row bins (global row = 4q + r)
        dst[(q * 4 + r) * 4] = token(w, w, 1.0f);

        if ((r & 1) == 0) {
            s2s = w; s2m = w;
        } else {
            // b=8: 2-row bins (global bin = 2q + (r>>1))
            s2s = f4add(s2s, w);
            s2m = f4max(s2m, w);
            dst[(16 + q * 2 + (r >> 1)) * 4] = token(s2s, s2m, 0.5f);

            if (r == 1) {
                s4s = s2s; s4m = s2m;
            } else {
                // b=4: 4-row bin (global bin = q)
                s4s = f4add(s4s, s2s);
                s4m = f4max(s4m, s2m);
                dst[(24 + q) * 4] = token(s4s, s4m, 0.25f);
            }
        }
    }

    // ---- b=2: combine quarter pairs (q with q^1) via lane^4 ----
    float4 s8s = f4add(s4s, f4shfl_xor(s4s, 4));
    float4 s8m = f4max(s4m, f4shfl_xor(s4m, 4));
    if ((q & 1) == 0) {
        dst[(28 + (q >> 1)) * 4] = token(s8s, s8m, 0.125f);
    }

    // ---- b=1: combine halves (q with q^2) via lane^8 ----
    float4 s16s = f4add(s8s, f4shfl_xor(s8s, 8));
    float4 s16m = f4max(s8m, f4shfl_xor(s8m, 8));
    if (q == 0) {
        dst[30 * 4] = token(s16s, s16m, 0.0625f);
    }
}

extern "C" void kernel_launch(void* const* d_in, const int* in_sizes, int n_in,
                              void* d_out, int out_size) {
    const float* x = (const float*)d_in[0];
    float* out = (float*)d_out;
    // 262144 tiles * 16 threads = 4,194,304 threads = 16384 blocks of 256 (exact)
    hwtp_kernel<<<(N_TILES * 16) / 256, 256>>>(x, out);
}